// round 1
// baseline (speedup 1.0000x reference)
#include <cuda_runtime.h>
#include <math.h>

#define S 2048
#define BSZ 4
#define E 1024
#define ZD 128
#define H 2048
#define CDIM (2*H + ZD)   /* 4224 */
#define M1 (S*BSZ)        /* 8192 */

// ---------------- scratch (static device globals; allocation-free) ----------
__device__ float g_u[(size_t)M1 * H];        // [r=s*B+b, h]
__device__ float g_v[(size_t)BSZ * S * H];   // [b, s, h]
__device__ float g_z[(size_t)M1 * ZD];       // [r, z]
__device__ float g_q[(size_t)BSZ * S * ZD];  // [b, s, z]
__device__ float g_k[(size_t)BSZ * S * ZD];  // [b, s, z]
__device__ float g_attn[(size_t)BSZ * S * S];// [b, i, j]
__device__ float g_o[(size_t)BSZ * S * H];   // [b, s, h]

__device__ __forceinline__ float silu_f(float x) {
    return x * (1.0f / (1.0f + __expf(-x)));
}

// =============================================================================
// Kernel 1: base = silu(X @ Wp^T + bp), scatter into u / v / z.
// X: [M1, E] row-major (K-major).  Wp: [CDIM, E] row-major (K-major).  NT GEMM.
// =============================================================================
__global__ __launch_bounds__(256) void k_proj(const float* __restrict__ X,
                                              const float* __restrict__ W,
                                              const float* __restrict__ bias) {
    __shared__ float As[16][132];
    __shared__ float Bs[16][132];
    const int bm = blockIdx.y * 128;
    const int bn = blockIdx.x * 128;
    const int t  = threadIdx.x;
    const int ty = t >> 4, tx = t & 15;

    float acc[8][8];
#pragma unroll
    for (int i = 0; i < 8; i++)
#pragma unroll
        for (int j = 0; j < 8; j++) acc[i][j] = 0.0f;

    for (int k0 = 0; k0 < E; k0 += 16) {
#pragma unroll
        for (int i = 0; i < 2; i++) {
            int f = t + i * 256;
            int row = f >> 2, c4 = f & 3;
            float4 a4 = *(const float4*)(X + (size_t)(bm + row) * E + k0 + c4 * 4);
            As[c4*4+0][row] = a4.x; As[c4*4+1][row] = a4.y;
            As[c4*4+2][row] = a4.z; As[c4*4+3][row] = a4.w;
            float4 b4 = *(const float4*)(W + (size_t)(bn + row) * E + k0 + c4 * 4);
            Bs[c4*4+0][row] = b4.x; Bs[c4*4+1][row] = b4.y;
            Bs[c4*4+2][row] = b4.z; Bs[c4*4+3][row] = b4.w;
        }
        __syncthreads();
#pragma unroll
        for (int k = 0; k < 16; k++) {
            float a[8], b[8];
            *(float4*)(a)     = *(const float4*)&As[k][ty*8];
            *(float4*)(a + 4) = *(const float4*)&As[k][ty*8 + 4];
            *(float4*)(b)     = *(const float4*)&Bs[k][tx*8];
            *(float4*)(b + 4) = *(const float4*)&Bs[k][tx*8 + 4];
#pragma unroll
            for (int i = 0; i < 8; i++)
#pragma unroll
                for (int j = 0; j < 8; j++)
                    acc[i][j] = fmaf(a[i], b[j], acc[i][j]);
        }
        __syncthreads();
    }

    // epilogue: bias + silu + scatter. Region is uniform per block (boundaries
    // at H=2048 and 2H=4096 are multiples of 128).
#pragma unroll
    for (int i = 0; i < 8; i++) {
        int r = bm + ty * 8 + i;
        int b = r & 3, s = r >> 2;
        float v8[8];
#pragma unroll
        for (int j = 0; j < 8; j++) {
            int c = bn + tx * 8 + j;
            v8[j] = silu_f(acc[i][j] + bias[c]);
        }
        int c0 = bn + tx * 8;
        float* dst;
        if (bn < H) {
            dst = g_u + (size_t)r * H + c0;
        } else if (bn < 2 * H) {
            dst = g_v + ((size_t)b * S + s) * H + (c0 - H);
        } else {
            dst = g_z + (size_t)r * ZD + (c0 - 2 * H);
        }
        *(float4*)(dst)     = *(float4*)(v8);
        *(float4*)(dst + 4) = *(float4*)(v8 + 4);
    }
}

// =============================================================================
// Kernel 2: q = z*gamma0 + beta0, k = z*gamma1 + beta1 (transpose to [b,s,z])
// =============================================================================
__global__ __launch_bounds__(256) void k_qk(const float* __restrict__ gamma,
                                            const float* __restrict__ beta) {
    int idx = blockIdx.x * 256 + threadIdx.x;  // over M1*ZD
    int r = idx >> 7, zc = idx & 127;
    float z = g_z[idx];
    int b = r & 3, s = r >> 2;
    size_t o = ((size_t)b * S + s) * ZD + zc;
    g_q[o] = fmaf(z, gamma[zc],      beta[zc]);
    g_k[o] = fmaf(z, gamma[ZD + zc], beta[ZD + zc]);
}

// =============================================================================
// Kernel 3: attn = relu(q@k^T / S + bias)^2 with causal mask (j<=i kept).
// Skips fully-masked upper-triangular blocks (never read downstream).
// =============================================================================
__global__ __launch_bounds__(256) void k_attn(const float* __restrict__ rpb) {
    const int bi = blockIdx.y, bj = blockIdx.x, b = blockIdx.z;
    if (bj > bi) return;  // fully above diagonal
    const int bm = bi * 128, bn = bj * 128;
    const float* Q = g_q + (size_t)b * S * ZD;
    const float* K = g_k + (size_t)b * S * ZD;

    __shared__ float As[16][132];
    __shared__ float Bs[16][132];
    const int t = threadIdx.x;
    const int ty = t >> 4, tx = t & 15;

    float acc[8][8];
#pragma unroll
    for (int i = 0; i < 8; i++)
#pragma unroll
        for (int j = 0; j < 8; j++) acc[i][j] = 0.0f;

    for (int k0 = 0; k0 < ZD; k0 += 16) {
#pragma unroll
        for (int i = 0; i < 2; i++) {
            int f = t + i * 256;
            int row = f >> 2, c4 = f & 3;
            float4 a4 = *(const float4*)(Q + (size_t)(bm + row) * ZD + k0 + c4 * 4);
            As[c4*4+0][row] = a4.x; As[c4*4+1][row] = a4.y;
            As[c4*4+2][row] = a4.z; As[c4*4+3][row] = a4.w;
            float4 b4 = *(const float4*)(K + (size_t)(bn + row) * ZD + k0 + c4 * 4);
            Bs[c4*4+0][row] = b4.x; Bs[c4*4+1][row] = b4.y;
            Bs[c4*4+2][row] = b4.z; Bs[c4*4+3][row] = b4.w;
        }
        __syncthreads();
#pragma unroll
        for (int k = 0; k < 16; k++) {
            float a[8], bb[8];
            *(float4*)(a)      = *(const float4*)&As[k][ty*8];
            *(float4*)(a + 4)  = *(const float4*)&As[k][ty*8 + 4];
            *(float4*)(bb)     = *(const float4*)&Bs[k][tx*8];
            *(float4*)(bb + 4) = *(const float4*)&Bs[k][tx*8 + 4];
#pragma unroll
            for (int i = 0; i < 8; i++)
#pragma unroll
                for (int j = 0; j < 8; j++)
                    acc[i][j] = fmaf(a[i], bb[j], acc[i][j]);
        }
        __syncthreads();
    }

    const float inv_s = 1.0f / (float)S;
    float* dstb = g_attn + (size_t)b * S * S;
#pragma unroll
    for (int i = 0; i < 8; i++) {
        int gi = bm + ty * 8 + i;
        float v8[8];
#pragma unroll
        for (int j = 0; j < 8; j++) {
            int gj = bn + tx * 8 + j;
            float val = acc[i][j] * inv_s + rpb[(2048 - 1) + gj - gi];
            float m = (gj <= gi) ? fmaxf(val, 0.0f) : 0.0f;
            v8[j] = m * m;
        }
        float* dst = dstb + (size_t)gi * S + bn + tx * 8;
        *(float4*)(dst)     = *(float4*)(v8);
        *(float4*)(dst + 4) = *(float4*)(v8 + 4);
    }
}

// =============================================================================
// Kernel 4: o[b] = attn[b] @ v[b].  NN GEMM, K-loop truncated at bm+128
// (attn row i is zero for j > i).
// =============================================================================
__global__ __launch_bounds__(256) void k_av() {
    const int b = blockIdx.z;
    const int bm = blockIdx.y * 128, bn = blockIdx.x * 128;
    const float* A = g_attn + (size_t)b * S * S;
    const float* V = g_v + (size_t)b * S * H;

    __shared__ float As[16][132];
    __shared__ float Bs[16][132];
    const int t = threadIdx.x;
    const int ty = t >> 4, tx = t & 15;

    float acc[8][8];
#pragma unroll
    for (int i = 0; i < 8; i++)
#pragma unroll
        for (int j = 0; j < 8; j++) acc[i][j] = 0.0f;

    const int kmax = bm + 128;  // causal truncation
    for (int k0 = 0; k0 < kmax; k0 += 16) {
#pragma unroll
        for (int i = 0; i < 2; i++) {
            int f = t + i * 256;
            // A tile (transpose into As): rows of attn, cols = k
            int row = f >> 2, c4 = f & 3;
            float4 a4 = *(const float4*)(A + (size_t)(bm + row) * S + k0 + c4 * 4);
            As[c4*4+0][row] = a4.x; As[c4*4+1][row] = a4.y;
            As[c4*4+2][row] = a4.z; As[c4*4+3][row] = a4.w;
            // B tile (direct): 16 rows of V, 128 cols
            int brow = f >> 5, bc4 = f & 31;
            float4 b4 = *(const float4*)(V + (size_t)(k0 + brow) * H + bn + bc4 * 4);
            *(float4*)&Bs[brow][bc4 * 4] = b4;
        }
        __syncthreads();
#pragma unroll
        for (int k = 0; k < 16; k++) {
            float a[8], bb[8];
            *(float4*)(a)      = *(const float4*)&As[k][ty*8];
            *(float4*)(a + 4)  = *(const float4*)&As[k][ty*8 + 4];
            *(float4*)(bb)     = *(const float4*)&Bs[k][tx*8];
            *(float4*)(bb + 4) = *(const float4*)&Bs[k][tx*8 + 4];
#pragma unroll
            for (int i = 0; i < 8; i++)
#pragma unroll
                for (int j = 0; j < 8; j++)
                    acc[i][j] = fmaf(a[i], bb[j], acc[i][j]);
        }
        __syncthreads();
    }

    float* Ob = g_o + (size_t)b * S * H;
#pragma unroll
    for (int i = 0; i < 8; i++) {
        int gi = bm + ty * 8 + i;
        float* dst = Ob + (size_t)gi * H + bn + tx * 8;
        *(float4*)(dst)     = *(float4*)(&acc[i][0]);
        *(float4*)(dst + 4) = *(float4*)(&acc[i][4]);
    }
}

// =============================================================================
// Kernel 5: out = (o*u) @ Wout^T + bout.  A built on the fly (gating fused).
// Wout: [E, H] row-major (K-major).  NT GEMM.
// =============================================================================
__global__ __launch_bounds__(256) void k_out(const float* __restrict__ W,
                                             const float* __restrict__ bout,
                                             float* __restrict__ out) {
    const int bm = blockIdx.y * 128, bn = blockIdx.x * 128;
    __shared__ float As[16][132];
    __shared__ float Bs[16][132];
    const int t = threadIdx.x;
    const int ty = t >> 4, tx = t & 15;

    float acc[8][8];
#pragma unroll
    for (int i = 0; i < 8; i++)
#pragma unroll
        for (int j = 0; j < 8; j++) acc[i][j] = 0.0f;

    for (int k0 = 0; k0 < H; k0 += 16) {
#pragma unroll
        for (int i = 0; i < 2; i++) {
            int f = t + i * 256;
            int row = f >> 2, c4 = f & 3;
            int r = bm + row;
            int bb_ = r & 3, ss = r >> 2;
            float4 o4 = *(const float4*)(g_o + ((size_t)bb_ * S + ss) * H + k0 + c4 * 4);
            float4 u4 = *(const float4*)(g_u + (size_t)r * H + k0 + c4 * 4);
            As[c4*4+0][row] = o4.x * u4.x; As[c4*4+1][row] = o4.y * u4.y;
            As[c4*4+2][row] = o4.z * u4.z; As[c4*4+3][row] = o4.w * u4.w;
            float4 b4 = *(const float4*)(W + (size_t)(bn + row) * H + k0 + c4 * 4);
            Bs[c4*4+0][row] = b4.x; Bs[c4*4+1][row] = b4.y;
            Bs[c4*4+2][row] = b4.z; Bs[c4*4+3][row] = b4.w;
        }
        __syncthreads();
#pragma unroll
        for (int k = 0; k < 16; k++) {
            float a[8], bb[8];
            *(float4*)(a)      = *(const float4*)&As[k][ty*8];
            *(float4*)(a + 4)  = *(const float4*)&As[k][ty*8 + 4];
            *(float4*)(bb)     = *(const float4*)&Bs[k][tx*8];
            *(float4*)(bb + 4) = *(const float4*)&Bs[k][tx*8 + 4];
#pragma unroll
            for (int i = 0; i < 8; i++)
#pragma unroll
                for (int j = 0; j < 8; j++)
                    acc[i][j] = fmaf(a[i], bb[j], acc[i][j]);
        }
        __syncthreads();
    }

#pragma unroll
    for (int i = 0; i < 8; i++) {
        int r = bm + ty * 8 + i;
        float v8[8];
#pragma unroll
        for (int j = 0; j < 8; j++) {
            int c = bn + tx * 8 + j;
            v8[j] = acc[i][j] + bout[c];
        }
        float* dst = out + (size_t)r * E + bn + tx * 8;
        *(float4*)(dst)     = *(float4*)(v8);
        *(float4*)(dst + 4) = *(float4*)(v8 + 4);
    }
}

// =============================================================================
extern "C" void kernel_launch(void* const* d_in, const int* in_sizes, int n_in,
                              void* d_out, int out_size) {
    (void)in_sizes; (void)n_in; (void)out_size;
    const float* x      = (const float*)d_in[0];
    // d_in[1] = attn_mask (bool) — causal mask computed analytically, unused
    const float* proj_w = (const float*)d_in[2];
    const float* proj_b = (const float*)d_in[3];
    const float* out_w  = (const float*)d_in[4];
    const float* out_b  = (const float*)d_in[5];
    const float* gamma  = (const float*)d_in[6];
    const float* beta   = (const float*)d_in[7];
    const float* rpb    = (const float*)d_in[8];
    float* out = (float*)d_out;

    k_proj<<<dim3(CDIM / 128, M1 / 128), 256>>>(x, proj_w, proj_b);
    k_qk  <<<(M1 * ZD) / 256, 256>>>(gamma, beta);
    k_attn<<<dim3(S / 128, S / 128, BSZ), 256>>>(rpb);
    k_av  <<<dim3(H / 128, S / 128, BSZ), 256>>>();
    k_out <<<dim3(E / 128, M1 / 128), 256>>>(out_w, out_b, out);
}

// round 2
// speedup vs baseline: 2.4773x; 2.4773x over previous
#include <cuda_runtime.h>
#include <math.h>

#define S 2048
#define BSZ 4
#define E 1024
#define ZD 128
#define H 2048
#define CDIM (2*H + ZD)   /* 4224 */
#define M1 (S*BSZ)        /* 8192 */

// ---------------- scratch (static device globals; allocation-free) ----------
__device__ float g_u[(size_t)M1 * H];
__device__ float g_v[(size_t)BSZ * S * H];
__device__ float g_z[(size_t)M1 * ZD];
__device__ float g_q[(size_t)BSZ * S * ZD];
__device__ float g_k[(size_t)BSZ * S * ZD];
__device__ float g_attn[(size_t)BSZ * S * S];
__device__ float g_o[(size_t)BSZ * S * H];

__device__ __forceinline__ float silu_f(float x) {
    return x * (1.0f / (1.0f + __expf(-x)));
}
__device__ __forceinline__ unsigned f2tf(float f) {
    unsigned u; asm("cvt.rna.tf32.f32 %0, %1;" : "=r"(u) : "f"(f)); return u;
}
__device__ __forceinline__ void mma8(float* c, const unsigned* a, const unsigned* b) {
    asm volatile("mma.sync.aligned.m16n8k8.row.col.f32.tf32.tf32.f32 "
        "{%0,%1,%2,%3}, {%4,%5,%6,%7}, {%8,%9}, {%0,%1,%2,%3};"
        : "+f"(c[0]), "+f"(c[1]), "+f"(c[2]), "+f"(c[3])
        : "r"(a[0]), "r"(a[1]), "r"(a[2]), "r"(a[3]), "r"(b[0]), "r"(b[1]));
}
__device__ __forceinline__ void sts4(unsigned* dst, float4 v) {
    uint4 u = make_uint4(f2tf(v.x), f2tf(v.y), f2tf(v.z), f2tf(v.w));
    *(uint4*)dst = u;
}

// Both A and B tiles stored as [row(m|n)][k] with pitch 20 (conflict-free frags)
__device__ __forceinline__ void compute_nt(const unsigned (*As)[20], const unsigned (*Bs)[20],
                                           float acc[4][4][4], int wm, int wn, int grp, int qid) {
#pragma unroll
    for (int kk = 0; kk < 16; kk += 8) {
        unsigned af[4][4], bf[4][2];
#pragma unroll
        for (int mi = 0; mi < 4; mi++) {
            int r = wm + mi * 16 + grp;
            af[mi][0] = As[r][kk + qid];
            af[mi][1] = As[r + 8][kk + qid];
            af[mi][2] = As[r][kk + qid + 4];
            af[mi][3] = As[r + 8][kk + qid + 4];
        }
#pragma unroll
        for (int ni = 0; ni < 4; ni++) {
            int r = wn + ni * 8 + grp;
            bf[ni][0] = Bs[r][kk + qid];
            bf[ni][1] = Bs[r][kk + qid + 4];
        }
#pragma unroll
        for (int mi = 0; mi < 4; mi++)
#pragma unroll
            for (int ni = 0; ni < 4; ni++)
                mma8(acc[mi][ni], af[mi], bf[ni]);
    }
}

// B tile in [k][n] layout, pitch 136 (qid*136 mod 32 = 8*qid -> conflict-free)
__device__ __forceinline__ void compute_nn(const unsigned (*As)[20], const unsigned (*Vs)[136],
                                           float acc[4][4][4], int wm, int wn, int grp, int qid) {
#pragma unroll
    for (int kk = 0; kk < 16; kk += 8) {
        unsigned af[4][4], bf[4][2];
#pragma unroll
        for (int mi = 0; mi < 4; mi++) {
            int r = wm + mi * 16 + grp;
            af[mi][0] = As[r][kk + qid];
            af[mi][1] = As[r + 8][kk + qid];
            af[mi][2] = As[r][kk + qid + 4];
            af[mi][3] = As[r + 8][kk + qid + 4];
        }
#pragma unroll
        for (int ni = 0; ni < 4; ni++) {
            int c = wn + ni * 8 + grp;
            bf[ni][0] = Vs[kk + qid][c];
            bf[ni][1] = Vs[kk + qid + 4][c];
        }
#pragma unroll
        for (int mi = 0; mi < 4; mi++)
#pragma unroll
            for (int ni = 0; ni < 4; ni++)
                mma8(acc[mi][ni], af[mi], bf[ni]);
    }
}

#define MMA_PROLOG                                                   \
    const int t = threadIdx.x, lane = t & 31, wid = t >> 5;          \
    const int wm = (wid >> 2) * 64, wn = (wid & 3) * 32;             \
    const int grp = lane >> 2, qid = lane & 3;                       \
    const int row0 = t >> 2, c4 = (t & 3) * 4;                       \
    float acc[4][4][4];                                              \
    _Pragma("unroll") for (int i = 0; i < 4; i++)                    \
    _Pragma("unroll") for (int j = 0; j < 4; j++)                    \
    _Pragma("unroll") for (int r = 0; r < 4; r++) acc[i][j][r] = 0.0f;

// =============================================================================
// Kernel 1: base = silu(X @ Wp^T + bp) -> scatter u/v/z.  NT, K=E=1024.
// =============================================================================
__global__ __launch_bounds__(256) void k_proj(const float* __restrict__ X,
                                              const float* __restrict__ W,
                                              const float* __restrict__ bias) {
    __shared__ unsigned As[128][20], Bs[128][20];
    const int bm = blockIdx.y * 128, bn = blockIdx.x * 128;
    MMA_PROLOG

    const float* pA0 = X + (size_t)(bm + row0) * E + c4;
    const float* pA1 = X + (size_t)(bm + row0 + 64) * E + c4;
    const float* pB0 = W + (size_t)(bn + row0) * E + c4;
    const float* pB1 = W + (size_t)(bn + row0 + 64) * E + c4;

    float4 ra0 = *(const float4*)pA0, ra1 = *(const float4*)pA1;
    float4 rb0 = *(const float4*)pB0, rb1 = *(const float4*)pB1;

    for (int k0 = 0; k0 < E; k0 += 16) {
        sts4(&As[row0][c4], ra0); sts4(&As[row0 + 64][c4], ra1);
        sts4(&Bs[row0][c4], rb0); sts4(&Bs[row0 + 64][c4], rb1);
        __syncthreads();
        if (k0 + 16 < E) {
            ra0 = *(const float4*)(pA0 + k0 + 16);
            ra1 = *(const float4*)(pA1 + k0 + 16);
            rb0 = *(const float4*)(pB0 + k0 + 16);
            rb1 = *(const float4*)(pB1 + k0 + 16);
        }
        compute_nt(As, Bs, acc, wm, wn, grp, qid);
        __syncthreads();
    }

#pragma unroll
    for (int mi = 0; mi < 4; mi++)
#pragma unroll
        for (int half = 0; half < 2; half++) {
            int r = bm + wm + mi * 16 + grp + half * 8;
            int b = r & 3, s = r >> 2;
#pragma unroll
            for (int ni = 0; ni < 4; ni++) {
                int c = bn + wn + ni * 8 + 2 * qid;
                float2 val;
                val.x = silu_f(acc[mi][ni][half * 2 + 0] + bias[c]);
                val.y = silu_f(acc[mi][ni][half * 2 + 1] + bias[c + 1]);
                if (bn < H)
                    *(float2*)(g_u + (size_t)r * H + c) = val;
                else if (bn < 2 * H)
                    *(float2*)(g_v + ((size_t)b * S + s) * H + (c - H)) = val;
                else
                    *(float2*)(g_z + (size_t)r * ZD + (c - 2 * H)) = val;
            }
        }
}

// =============================================================================
// Kernel 2: q/k affine (elementwise)
// =============================================================================
__global__ __launch_bounds__(256) void k_qk(const float* __restrict__ gamma,
                                            const float* __restrict__ beta) {
    int idx = blockIdx.x * 256 + threadIdx.x;
    int r = idx >> 7, zc = idx & 127;
    float z = g_z[idx];
    int b = r & 3, s = r >> 2;
    size_t o = ((size_t)b * S + s) * ZD + zc;
    g_q[o] = fmaf(z, gamma[zc],      beta[zc]);
    g_k[o] = fmaf(z, gamma[ZD + zc], beta[ZD + zc]);
}

// =============================================================================
// Kernel 3: attn = relu(q@k^T/S + bias)^2, causal. NT, K=ZD=128, skip upper blocks.
// =============================================================================
__global__ __launch_bounds__(256) void k_attn(const float* __restrict__ rpb) {
    const int bi = blockIdx.y, bj = blockIdx.x, b = blockIdx.z;
    if (bj > bi) return;
    __shared__ unsigned As[128][20], Bs[128][20];
    const int bm = bi * 128, bn = bj * 128;
    const float* Q = g_q + (size_t)b * S * ZD;
    const float* K = g_k + (size_t)b * S * ZD;
    MMA_PROLOG

    const float* pA0 = Q + (size_t)(bm + row0) * ZD + c4;
    const float* pA1 = Q + (size_t)(bm + row0 + 64) * ZD + c4;
    const float* pB0 = K + (size_t)(bn + row0) * ZD + c4;
    const float* pB1 = K + (size_t)(bn + row0 + 64) * ZD + c4;

    float4 ra0 = *(const float4*)pA0, ra1 = *(const float4*)pA1;
    float4 rb0 = *(const float4*)pB0, rb1 = *(const float4*)pB1;

    for (int k0 = 0; k0 < ZD; k0 += 16) {
        sts4(&As[row0][c4], ra0); sts4(&As[row0 + 64][c4], ra1);
        sts4(&Bs[row0][c4], rb0); sts4(&Bs[row0 + 64][c4], rb1);
        __syncthreads();
        if (k0 + 16 < ZD) {
            ra0 = *(const float4*)(pA0 + k0 + 16);
            ra1 = *(const float4*)(pA1 + k0 + 16);
            rb0 = *(const float4*)(pB0 + k0 + 16);
            rb1 = *(const float4*)(pB1 + k0 + 16);
        }
        compute_nt(As, Bs, acc, wm, wn, grp, qid);
        __syncthreads();
    }

    const float inv_s = 1.0f / (float)S;
    float* dstb = g_attn + (size_t)b * S * S;
#pragma unroll
    for (int mi = 0; mi < 4; mi++)
#pragma unroll
        for (int half = 0; half < 2; half++) {
            int gi = bm + wm + mi * 16 + grp + half * 8;
#pragma unroll
            for (int ni = 0; ni < 4; ni++) {
                int gj = bn + wn + ni * 8 + 2 * qid;
                float v0 = acc[mi][ni][half * 2 + 0] * inv_s + rpb[2047 + gj - gi];
                float v1 = acc[mi][ni][half * 2 + 1] * inv_s + rpb[2047 + gj + 1 - gi];
                float m0 = (gj     <= gi) ? fmaxf(v0, 0.0f) : 0.0f;
                float m1 = (gj + 1 <= gi) ? fmaxf(v1, 0.0f) : 0.0f;
                *(float2*)(dstb + (size_t)gi * S + gj) = make_float2(m0 * m0, m1 * m1);
            }
        }
}

// =============================================================================
// Kernel 4: o = attn @ v.  NN (V kept [k][n]), causal-truncated K loop.
// =============================================================================
__global__ __launch_bounds__(256) void k_av() {
    const int b = blockIdx.z;
    const int bm = blockIdx.y * 128, bn = blockIdx.x * 128;
    const float* A = g_attn + (size_t)b * S * S;
    const float* V = g_v + (size_t)b * S * H;
    __shared__ unsigned As[128][20];
    __shared__ unsigned Vs[16][136];
    MMA_PROLOG
    const int vrow = t >> 5, vc4 = (t & 31) * 4;

    const float* pA0 = A + (size_t)(bm + row0) * S + c4;
    const float* pA1 = A + (size_t)(bm + row0 + 64) * S + c4;

    const int kmax = bm + 128;
    float4 ra0 = *(const float4*)pA0, ra1 = *(const float4*)pA1;
    float4 rv0 = *(const float4*)(V + (size_t)(vrow) * H + bn + vc4);
    float4 rv1 = *(const float4*)(V + (size_t)(vrow + 8) * H + bn + vc4);

    for (int k0 = 0; k0 < kmax; k0 += 16) {
        sts4(&As[row0][c4], ra0); sts4(&As[row0 + 64][c4], ra1);
        sts4(&Vs[vrow][vc4], rv0); sts4(&Vs[vrow + 8][vc4], rv1);
        __syncthreads();
        if (k0 + 16 < kmax) {
            ra0 = *(const float4*)(pA0 + k0 + 16);
            ra1 = *(const float4*)(pA1 + k0 + 16);
            rv0 = *(const float4*)(V + (size_t)(k0 + 16 + vrow) * H + bn + vc4);
            rv1 = *(const float4*)(V + (size_t)(k0 + 16 + vrow + 8) * H + bn + vc4);
        }
        compute_nn(As, Vs, acc, wm, wn, grp, qid);
        __syncthreads();
    }

    float* Ob = g_o + (size_t)b * S * H;
#pragma unroll
    for (int mi = 0; mi < 4; mi++)
#pragma unroll
        for (int half = 0; half < 2; half++) {
            int gi = bm + wm + mi * 16 + grp + half * 8;
#pragma unroll
            for (int ni = 0; ni < 4; ni++) {
                int c = bn + wn + ni * 8 + 2 * qid;
                *(float2*)(Ob + (size_t)gi * H + c) =
                    make_float2(acc[mi][ni][half * 2 + 0], acc[mi][ni][half * 2 + 1]);
            }
        }
}

// =============================================================================
// Kernel 5: out = (o*u) @ Wout^T + bout.  NT, K=H=2048, gating fused into A fill.
// =============================================================================
__global__ __launch_bounds__(256) void k_out(const float* __restrict__ W,
                                             const float* __restrict__ bout,
                                             float* __restrict__ out) {
    const int bm = blockIdx.y * 128, bn = blockIdx.x * 128;
    __shared__ unsigned As[128][20], Bs[128][20];
    MMA_PROLOG

    const int r0 = bm + row0;
    const int r1 = r0 + 64;
    const float* pO0 = g_o + ((size_t)(r0 & 3) * S + (r0 >> 2)) * H + c4;
    const float* pO1 = g_o + ((size_t)(r1 & 3) * S + (r1 >> 2)) * H + c4;
    const float* pU0 = g_u + (size_t)r0 * H + c4;
    const float* pU1 = g_u + (size_t)r1 * H + c4;
    const float* pB0 = W + (size_t)(bn + row0) * H + c4;
    const float* pB1 = W + (size_t)(bn + row0 + 64) * H + c4;

    float4 ra0, ra1, rb0, rb1;
    {
        float4 o0 = *(const float4*)pO0, u0 = *(const float4*)pU0;
        float4 o1 = *(const float4*)pO1, u1 = *(const float4*)pU1;
        ra0 = make_float4(o0.x * u0.x, o0.y * u0.y, o0.z * u0.z, o0.w * u0.w);
        ra1 = make_float4(o1.x * u1.x, o1.y * u1.y, o1.z * u1.z, o1.w * u1.w);
        rb0 = *(const float4*)pB0; rb1 = *(const float4*)pB1;
    }

    for (int k0 = 0; k0 < H; k0 += 16) {
        sts4(&As[row0][c4], ra0); sts4(&As[row0 + 64][c4], ra1);
        sts4(&Bs[row0][c4], rb0); sts4(&Bs[row0 + 64][c4], rb1);
        __syncthreads();
        if (k0 + 16 < H) {
            float4 o0 = *(const float4*)(pO0 + k0 + 16), u0 = *(const float4*)(pU0 + k0 + 16);
            float4 o1 = *(const float4*)(pO1 + k0 + 16), u1 = *(const float4*)(pU1 + k0 + 16);
            ra0 = make_float4(o0.x * u0.x, o0.y * u0.y, o0.z * u0.z, o0.w * u0.w);
            ra1 = make_float4(o1.x * u1.x, o1.y * u1.y, o1.z * u1.z, o1.w * u1.w);
            rb0 = *(const float4*)(pB0 + k0 + 16);
            rb1 = *(const float4*)(pB1 + k0 + 16);
        }
        compute_nt(As, Bs, acc, wm, wn, grp, qid);
        __syncthreads();
    }

#pragma unroll
    for (int mi = 0; mi < 4; mi++)
#pragma unroll
        for (int half = 0; half < 2; half++) {
            int r = bm + wm + mi * 16 + grp + half * 8;
#pragma unroll
            for (int ni = 0; ni < 4; ni++) {
                int c = bn + wn + ni * 8 + 2 * qid;
                float2 val;
                val.x = acc[mi][ni][half * 2 + 0] + bout[c];
                val.y = acc[mi][ni][half * 2 + 1] + bout[c + 1];
                *(float2*)(out + (size_t)r * E + c) = val;
            }
        }
}

// =============================================================================
extern "C" void kernel_launch(void* const* d_in, const int* in_sizes, int n_in,
                              void* d_out, int out_size) {
    (void)in_sizes; (void)n_in; (void)out_size;
    const float* x      = (const float*)d_in[0];
    const float* proj_w = (const float*)d_in[2];
    const float* proj_b = (const float*)d_in[3];
    const float* out_w  = (const float*)d_in[4];
    const float* out_b  = (const float*)d_in[5];
    const float* gamma  = (const float*)d_in[6];
    const float* beta   = (const float*)d_in[7];
    const float* rpb    = (const float*)d_in[8];
    float* out = (float*)d_out;

    k_proj<<<dim3(CDIM / 128, M1 / 128), 256>>>(x, proj_w, proj_b);
    k_qk  <<<(M1 * ZD) / 256, 256>>>(gamma, beta);
    k_attn<<<dim3(S / 128, S / 128, BSZ), 256>>>(rpb);
    k_av  <<<dim3(H / 128, S / 128, BSZ), 256>>>();
    k_out <<<dim3(E / 128, M1 / 128), 256>>>(out_w, out_b, out);
}

// round 4
// speedup vs baseline: 7.1765x; 2.8969x over previous
#include <cuda_runtime.h>
#include <cuda_fp16.h>
#include <math.h>
#include <stdint.h>

#define S 2048
#define BSZ 4
#define E 1024
#define ZD 128
#define H 2048
#define CDIM (2*H + ZD)   /* 4224 */
#define M1 (S*BSZ)        /* 8192 */

#define KT 64                    /* halves per k-stage = 128 B per row */
#define TILE_B (128*128)         /* one 128-row x 128-B tile = 16 KB */
#define STAGE_B (2*TILE_B)       /* A + B = 32 KB */
#define DYN_SMEM (2*STAGE_B + 1024)

// ---------------- scratch (static device globals; allocation-free) ----------
__device__ __half g_x16 [(size_t)M1 * E];
__device__ __half g_wp16[(size_t)CDIM * E];
__device__ __half g_wo16[(size_t)E * H];
__device__ __half g_u16 [(size_t)M1 * H];
__device__ __half g_v16 [(size_t)BSZ * S * H];
__device__ __half g_vt16[(size_t)BSZ * H * S];
__device__ __half g_q16 [(size_t)BSZ * S * ZD];
__device__ __half g_k16 [(size_t)BSZ * S * ZD];
__device__ __half g_at16[(size_t)BSZ * S * S];
__device__ __half g_go16[(size_t)M1 * H];

// ---------------- helpers ----------------------------------------------------
__device__ __forceinline__ float silu_f(float x) {
    return x * (1.0f / (1.0f + __expf(-x)));
}
__device__ __forceinline__ uint32_t smem_u32(const void* p) {
    uint32_t a;
    asm("{ .reg .u64 t; cvta.to.shared.u64 t, %1; cvt.u32.u64 %0, t; }"
        : "=r"(a) : "l"(p));
    return a;
}
#define SWZ(o) ((o) ^ (((o) >> 3) & 0x70))

__device__ __forceinline__ void ldsm4(uint32_t* r, uint32_t addr) {
    asm volatile("ldmatrix.sync.aligned.m8n8.x4.shared.b16 {%0,%1,%2,%3}, [%4];"
                 : "=r"(r[0]), "=r"(r[1]), "=r"(r[2]), "=r"(r[3]) : "r"(addr));
}
__device__ __forceinline__ void mma16(float* c, const uint32_t* a, const uint32_t* b) {
    asm volatile("mma.sync.aligned.m16n8k16.row.col.f32.f16.f16.f32 "
        "{%0,%1,%2,%3}, {%4,%5,%6,%7}, {%8,%9}, {%0,%1,%2,%3};"
        : "+f"(c[0]), "+f"(c[1]), "+f"(c[2]), "+f"(c[3])
        : "r"(a[0]), "r"(a[1]), "r"(a[2]), "r"(a[3]), "r"(b[0]), "r"(b[1]));
}
__device__ __forceinline__ void cpa16(uint32_t dst, const void* src) {
    asm volatile("cp.async.cg.shared.global [%0], [%1], 16;" :: "r"(dst), "l"(src));
}

// Load one 128x64h A tile + one 128x64h B tile (both K-major, SW128-swizzled).
__device__ __forceinline__ void tile_loads(uint32_t dbase, int buf,
                                           const __half* A, size_t lda,
                                           const __half* B, size_t ldb,
                                           int kt, int tid) {
    uint32_t ad = dbase + buf * STAGE_B;
    uint32_t bd = ad + TILE_B;
#pragma unroll
    for (int i = 0; i < 4; i++) {
        int id = tid + i * 256;
        int row = id >> 3, c = id & 7;
        uint32_t off = SWZ((uint32_t)(row * 128 + c * 16));
        cpa16(ad + off, A + (size_t)row * lda + kt * KT + c * 8);
        cpa16(bd + off, B + (size_t)row * ldb + kt * KT + c * 8);
    }
}

// Warp tile 64x32, k16 steps via ldmatrix.x4 + m16n8k16 HMMA.
__device__ __forceinline__ void compute_stage(uint32_t ad, uint32_t bd,
                                              float acc[4][4][4],
                                              int wm, int wn, int lane) {
    const int arow = lane & 15;
    const int akh  = (lane >> 4) << 4;                     // +16 B for k+8 half
    const int brow = (lane & 7) + ((lane >> 4) << 3);
    const int bkh  = ((lane >> 3) & 1) << 4;
#pragma unroll
    for (int kk = 0; kk < 128; kk += 32) {                 // 32 B = k16
        uint32_t a[4][4], b[2][4];
#pragma unroll
        for (int mi = 0; mi < 4; mi++) {
            uint32_t o = (uint32_t)((wm + mi * 16 + arow) * 128 + kk + akh);
            ldsm4(a[mi], ad + SWZ(o));
        }
#pragma unroll
        for (int np = 0; np < 2; np++) {
            uint32_t o = (uint32_t)((wn + np * 16 + brow) * 128 + kk + bkh);
            ldsm4(b[np], bd + SWZ(o));
        }
#pragma unroll
        for (int mi = 0; mi < 4; mi++)
#pragma unroll
            for (int ni = 0; ni < 4; ni++)
                mma16(acc[mi][ni], a[mi], &b[ni >> 1][(ni & 1) * 2]);
    }
}

// Double-buffered mainloop.
__device__ __forceinline__ void run_gemm(uint32_t dbase,
                                         const __half* A, size_t lda,
                                         const __half* B, size_t ldb,
                                         int NK, float acc[4][4][4],
                                         int wm, int wn, int tid, int lane) {
    tile_loads(dbase, 0, A, lda, B, ldb, 0, tid);
    asm volatile("cp.async.commit_group;" ::: "memory");
    for (int kt = 0; kt < NK; kt++) {
        if (kt + 1 < NK) {
            tile_loads(dbase, (kt + 1) & 1, A, lda, B, ldb, kt + 1, tid);
            asm volatile("cp.async.commit_group;" ::: "memory");
            asm volatile("cp.async.wait_group 1;" ::: "memory");
        } else {
            asm volatile("cp.async.wait_group 0;" ::: "memory");
        }
        __syncthreads();
        uint32_t sb = dbase + (kt & 1) * STAGE_B;
        compute_stage(sb, sb + TILE_B, acc, wm, wn, lane);
        __syncthreads();
    }
}

#define GEMM_PROLOG                                                         \
    extern __shared__ char dsm[];                                           \
    const int tid = threadIdx.x, lane = tid & 31, wid = tid >> 5;           \
    const int wm = (wid >> 2) * 64, wn = (wid & 3) * 32;                    \
    const int grp = lane >> 2, qid = lane & 3;                              \
    uint32_t dbase = (smem_u32(dsm) + 1023) & ~1023u;                       \
    float acc[4][4][4];                                                     \
    _Pragma("unroll") for (int i_ = 0; i_ < 4; i_++)                        \
    _Pragma("unroll") for (int j_ = 0; j_ < 4; j_++)                        \
    _Pragma("unroll") for (int r_ = 0; r_ < 4; r_++) acc[i_][j_][r_] = 0.0f;

// =============================================================================
// k_cvt: fp32 -> fp16
// =============================================================================
__global__ __launch_bounds__(256) void k_cvt(const float* __restrict__ s,
                                             __half* __restrict__ d, int n4) {
    int i = blockIdx.x * 256 + threadIdx.x;
    if (i < n4) {
        float4 v = ((const float4*)s)[i];
        ((__half2*)d)[2 * i]     = __floats2half2_rn(v.x, v.y);
        ((__half2*)d)[2 * i + 1] = __floats2half2_rn(v.z, v.w);
    }
}

// =============================================================================
// Kernel 1: base = silu(x16 @ wp16^T + bias) -> u16 / v16 / (q16,k16 fused)
// =============================================================================
__global__ __launch_bounds__(256) void k_proj(const float* __restrict__ bias,
                                              const float* __restrict__ gamma,
                                              const float* __restrict__ beta) {
    const int bm = blockIdx.y * 128, bn = blockIdx.x * 128;
    GEMM_PROLOG
    run_gemm(dbase, g_x16 + (size_t)bm * E, E, g_wp16 + (size_t)bn * E, E,
             E / KT, acc, wm, wn, tid, lane);

#pragma unroll
    for (int mi = 0; mi < 4; mi++)
#pragma unroll
        for (int half = 0; half < 2; half++) {
            int r = bm + wm + mi * 16 + grp + half * 8;
            int b = r & 3, sidx = r >> 2;
#pragma unroll
            for (int ni = 0; ni < 4; ni++) {
                int c = bn + wn + ni * 8 + 2 * qid;
                float v0 = silu_f(acc[mi][ni][half * 2 + 0] + bias[c]);
                float v1 = silu_f(acc[mi][ni][half * 2 + 1] + bias[c + 1]);
                if (bn < H) {
                    *(__half2*)(g_u16 + (size_t)r * H + c) = __floats2half2_rn(v0, v1);
                } else if (bn < 2 * H) {
                    *(__half2*)(g_v16 + ((size_t)b * S + sidx) * H + (c - H)) =
                        __floats2half2_rn(v0, v1);
                } else {
                    int zc = c - 2 * H;
                    float q0 = fmaf(v0, gamma[zc],     beta[zc]);
                    float q1 = fmaf(v1, gamma[zc + 1], beta[zc + 1]);
                    float k0 = fmaf(v0, gamma[ZD + zc],     beta[ZD + zc]);
                    float k1 = fmaf(v1, gamma[ZD + zc + 1], beta[ZD + zc + 1]);
                    size_t o = ((size_t)b * S + sidx) * ZD + zc;
                    *(__half2*)(g_q16 + o) = __floats2half2_rn(q0, q1);
                    *(__half2*)(g_k16 + o) = __floats2half2_rn(k0, k1);
                }
            }
        }
}

// =============================================================================
// Kernel 2: vt16[b][h][s] = v16[b][s][h]  (64x64 tiles)
// =============================================================================
__global__ __launch_bounds__(256) void k_vt() {
    __shared__ __half sm[64][72];
    int b = blockIdx.z, h0 = blockIdx.x * 64, s0 = blockIdx.y * 64;
    int tid = threadIdx.x;
    const __half* src = g_v16 + (size_t)b * S * H;
    int sl = tid >> 5, h2 = tid & 31;
#pragma unroll
    for (int i = 0; i < 8; i++) {
        __half2 v = *(const __half2*)(src + (size_t)(s0 + sl + 8 * i) * H + h0 + 2 * h2);
        sm[sl + 8 * i][2 * h2]     = __low2half(v);
        sm[sl + 8 * i][2 * h2 + 1] = __high2half(v);
    }
    __syncthreads();
    __half* dst = g_vt16 + (size_t)b * H * S;
    int hl = tid >> 5, s2 = tid & 31;
#pragma unroll
    for (int i = 0; i < 8; i++) {
        int h = hl + 8 * i;
        __half2 v = __halves2half2(sm[2 * s2][h], sm[2 * s2 + 1][h]);
        *(__half2*)(dst + (size_t)(h0 + h) * S + s0 + 2 * s2) = v;
    }
}

// =============================================================================
// Kernel 3: attn = relu(q@k^T/S + rpb)^2, causal, skip upper blocks
// =============================================================================
__global__ __launch_bounds__(256) void k_attn(const float* __restrict__ rpb) {
    const int bi = blockIdx.y, bj = blockIdx.x, b = blockIdx.z;
    if (bj > bi) return;
    const int bm = bi * 128, bn = bj * 128;
    GEMM_PROLOG
    run_gemm(dbase, g_q16 + ((size_t)b * S + bm) * ZD, ZD,
             g_k16 + ((size_t)b * S + bn) * ZD, ZD, ZD / KT, acc, wm, wn, tid, lane);

    const float inv_s = 1.0f / (float)S;
    __half* dstb = g_at16 + (size_t)b * S * S;
#pragma unroll
    for (int mi = 0; mi < 4; mi++)
#pragma unroll
        for (int half = 0; half < 2; half++) {
            int gi = bm + wm + mi * 16 + grp + half * 8;
#pragma unroll
            for (int ni = 0; ni < 4; ni++) {
                int gj = bn + wn + ni * 8 + 2 * qid;
                float v0 = acc[mi][ni][half * 2 + 0] * inv_s + rpb[2047 + gj - gi];
                float v1 = acc[mi][ni][half * 2 + 1] * inv_s + rpb[2047 + gj + 1 - gi];
                float m0 = (gj     <= gi) ? fmaxf(v0, 0.0f) : 0.0f;
                float m1 = (gj + 1 <= gi) ? fmaxf(v1, 0.0f) : 0.0f;
                *(__half2*)(dstb + (size_t)gi * S + gj) =
                    __floats2half2_rn(m0 * m0, m1 * m1);
            }
        }
}

// =============================================================================
// Kernel 4: go = (attn @ v) * u   (gating fused), causal-truncated K
// =============================================================================
__global__ __launch_bounds__(256) void k_av() {
    const int b = blockIdx.z;
    const int bm = blockIdx.y * 128, bn = blockIdx.x * 128;
    GEMM_PROLOG
    const int NK = 2 * (blockIdx.y + 1);   // K up to bm+128
    run_gemm(dbase, g_at16 + (size_t)b * S * S + (size_t)bm * S, S,
             g_vt16 + ((size_t)b * H + bn) * S, S, NK, acc, wm, wn, tid, lane);

#pragma unroll
    for (int mi = 0; mi < 4; mi++)
#pragma unroll
        for (int half = 0; half < 2; half++) {
            int sv = bm + wm + mi * 16 + grp + half * 8;
            int r = sv * 4 + b;
#pragma unroll
            for (int ni = 0; ni < 4; ni++) {
                int c = bn + wn + ni * 8 + 2 * qid;
                __half2 u2 = *(const __half2*)(g_u16 + (size_t)r * H + c);
                float g0 = acc[mi][ni][half * 2 + 0] * __low2float(u2);
                float g1 = acc[mi][ni][half * 2 + 1] * __high2float(u2);
                *(__half2*)(g_go16 + (size_t)r * H + c) = __floats2half2_rn(g0, g1);
            }
        }
}

// =============================================================================
// Kernel 5: out = go @ wo16^T + bout   (fp32 output)
// =============================================================================
__global__ __launch_bounds__(256) void k_out(const float* __restrict__ bout,
                                             float* __restrict__ out) {
    const int bm = blockIdx.y * 128, bn = blockIdx.x * 128;
    GEMM_PROLOG
    run_gemm(dbase, g_go16 + (size_t)bm * H, H, g_wo16 + (size_t)bn * H, H,
             H / KT, acc, wm, wn, tid, lane);

#pragma unroll
    for (int mi = 0; mi < 4; mi++)
#pragma unroll
        for (int half = 0; half < 2; half++) {
            int r = bm + wm + mi * 16 + grp + half * 8;
#pragma unroll
            for (int ni = 0; ni < 4; ni++) {
                int c = bn + wn + ni * 8 + 2 * qid;
                float2 v;
                v.x = acc[mi][ni][half * 2 + 0] + bout[c];
                v.y = acc[mi][ni][half * 2 + 1] + bout[c + 1];
                *(float2*)(out + (size_t)r * E + c) = v;
            }
        }
}

// =============================================================================
extern "C" void kernel_launch(void* const* d_in, const int* in_sizes, int n_in,
                              void* d_out, int out_size) {
    (void)in_sizes; (void)n_in; (void)out_size;
    const float* x      = (const float*)d_in[0];
    const float* proj_w = (const float*)d_in[2];
    const float* proj_b = (const float*)d_in[3];
    const float* out_w  = (const float*)d_in[4];
    const float* out_b  = (const float*)d_in[5];
    const float* gamma  = (const float*)d_in[6];
    const float* beta   = (const float*)d_in[7];
    const float* rpb    = (const float*)d_in[8];
    float* out = (float*)d_out;

    cudaFuncSetAttribute(k_proj, cudaFuncAttributeMaxDynamicSharedMemorySize, DYN_SMEM);
    cudaFuncSetAttribute(k_attn, cudaFuncAttributeMaxDynamicSharedMemorySize, DYN_SMEM);
    cudaFuncSetAttribute(k_av,   cudaFuncAttributeMaxDynamicSharedMemorySize, DYN_SMEM);
    cudaFuncSetAttribute(k_out,  cudaFuncAttributeMaxDynamicSharedMemorySize, DYN_SMEM);

    __half* x16;  cudaGetSymbolAddress((void**)&x16,  g_x16);
    __half* wp16; cudaGetSymbolAddress((void**)&wp16, g_wp16);
    __half* wo16; cudaGetSymbolAddress((void**)&wo16, g_wo16);

    k_cvt<<<(M1 * E / 4 + 255) / 256, 256>>>(x, x16, M1 * E / 4);
    k_cvt<<<(CDIM * E / 4 + 255) / 256, 256>>>(proj_w, wp16, CDIM * E / 4);
    k_cvt<<<(E * H / 4 + 255) / 256, 256>>>(out_w, wo16, E * H / 4);

    k_proj<<<dim3(CDIM / 128, M1 / 128), 256, DYN_SMEM>>>(proj_b, gamma, beta);
    k_vt  <<<dim3(H / 64, S / 64, BSZ), 256>>>();
    k_attn<<<dim3(S / 128, S / 128, BSZ), 256, DYN_SMEM>>>(rpb);
    k_av  <<<dim3(H / 128, S / 128, BSZ), 256, DYN_SMEM>>>();
    k_out <<<dim3(E / 128, M1 / 128), 256, DYN_SMEM>>>(out_b, out);
}